// round 7
// baseline (speedup 1.0000x reference)
#include <cuda_runtime.h>
#include <math.h>
#include <stdint.h>

#define NN 50000
#define NE 800000
#define FIN 128
#define D1 256
#define D2 128
#define KC 32

typedef unsigned long long ull;

// packed f32x2 FMA: d.lo = a.lo*b.lo + d.lo ; d.hi = a.hi*b.hi + d.hi
__device__ __forceinline__ void fma2(ull& d, ull a, ull b) {
    asm("fma.rn.f32x2 %0, %1, %2, %3;" : "=l"(d) : "l"(a), "l"(b), "l"(d));
}
__device__ __forceinline__ float ull_lo(ull v) { return __uint_as_float((unsigned)v); }
__device__ __forceinline__ float ull_hi(ull v) { return __uint_as_float((unsigned)(v >> 32)); }

// ---------------- scratch (device globals) ----------------
__device__ __align__(16) float g_aggX[(size_t)NN * FIN];  // normalized (A+I) agg of features
__device__ __align__(16) float g_abs[(size_t)NN * D2];    // tanh(aggX@Wc+bc)
__device__ __align__(16) float g_S[(size_t)NN * KC];      // softmax assign
__device__ __align__(16) float g_Wc[FIN * D2];            // W1 @ fc1W  (128x128) [k][n]
__device__ float g_bc[D2];                                 // b1 @ fc1W + fc1b
__device__ float g_cs[FIN];                                // colsum(aggX)
__device__ int   g_deg_in[NN], g_deg_out[NN];
__device__ int   g_off_in[NN + 1], g_off_out[NN + 1];
__device__ int   g_cur_in[NN], g_cur_out[NN];
__device__ int   g_src_in[NE];             // CSR by target: source ids
__device__ int   g_dst_out[NE];            // CSR by source: target ids
__device__ float g_dinv1[NN], g_dinv2[NN];
__device__ float g_adj[KC * KC];

// ---------------- init ----------------
__global__ void k_zero() {
    int i = blockIdx.x * blockDim.x + threadIdx.x;
    int stride = gridDim.x * blockDim.x;
    for (int j = i; j < NN; j += stride) {
        g_deg_in[j] = 0; g_deg_out[j] = 0;
        g_cur_in[j] = 0; g_cur_out[j] = 0;
    }
    if (i < KC * KC) g_adj[i] = 0.f;
    if (i < FIN) g_cs[i] = 0.f;
}

__global__ void k_degree(const int* __restrict__ e) {
    int i = blockIdx.x * blockDim.x + threadIdx.x;
    int stride = gridDim.x * blockDim.x;
    for (int j = i; j < NE; j += stride) {
        atomicAdd(&g_deg_out[e[j]], 1);
        atomicAdd(&g_deg_in[e[NE + j]], 1);
    }
}

// tiled block scan: block 0 scans deg_in, block 1 scans deg_out
__global__ __launch_bounds__(1024) void k_scan2() {
    const int* cnt = blockIdx.x ? g_deg_out : g_deg_in;
    int* off = blockIdx.x ? g_off_out : g_off_in;
    __shared__ int wsum[32];
    __shared__ int carry;
    int t = threadIdx.x;
    int lane = t & 31, w = t >> 5;
    if (t == 0) carry = 0;
    __syncthreads();
    for (int base = 0; base < NN; base += 1024) {
        int idx = base + t;
        int v = (idx < NN) ? cnt[idx] : 0;
        int x = v;
        #pragma unroll
        for (int o = 1; o < 32; o <<= 1) {
            int y = __shfl_up_sync(0xffffffffu, x, o);
            if (lane >= o) x += y;
        }
        if (lane == 31) wsum[w] = x;
        __syncthreads();
        if (w == 0) {
            int s = wsum[lane];
            #pragma unroll
            for (int o = 1; o < 32; o <<= 1) {
                int y = __shfl_up_sync(0xffffffffu, s, o);
                if (lane >= o) s += y;
            }
            wsum[lane] = s;
        }
        __syncthreads();
        int incl = x + (w ? wsum[w - 1] : 0);
        if (idx < NN) off[idx] = carry + incl - v;
        int total = wsum[31];
        __syncthreads();
        if (t == 0) carry += total;
        __syncthreads();
    }
    if (t == 0) off[NN] = carry;
}

__global__ void k_dinv() {
    int i = blockIdx.x * blockDim.x + threadIdx.x;
    int stride = gridDim.x * blockDim.x;
    for (int j = i; j < NN; j += stride) {
        g_dinv1[j] = rsqrtf((float)(g_deg_in[j] + 1)); // self-loop included
        int d = g_deg_out[j];
        g_dinv2[j] = (d > 0) ? rsqrtf((float)d) : 0.f;
    }
}

__global__ void k_fill(const int* __restrict__ e) {
    int i = blockIdx.x * blockDim.x + threadIdx.x;
    int stride = gridDim.x * blockDim.x;
    for (int j = i; j < NE; j += stride) {
        int r = e[j];
        int c = e[NE + j];
        int p = atomicAdd(&g_cur_in[c], 1);
        g_src_in[g_off_in[c] + p] = r;
        int q = atomicAdd(&g_cur_out[r], 1);
        g_dst_out[g_off_out[r] + q] = c;
    }
}

// ---------------- feature aggregation: aggX[i] = di*(sum ds*X[s] + di*X[i]) ----------------
__global__ __launch_bounds__(256) void k_agg(const float* __restrict__ X) {
    int i = blockIdx.x * 8 + (threadIdx.x >> 5);
    int lane = threadIdx.x & 31;
    if (i >= NN) return;
    float di = g_dinv1[i];
    const float4* X4 = (const float4*)X;
    float4 x = X4[(size_t)i * 32 + lane];
    float4 acc = make_float4(di * x.x, di * x.y, di * x.z, di * x.w);
    int s0 = g_off_in[i], s1 = g_off_in[i + 1];
    for (int idx = s0; idx < s1; idx++) {
        int s = g_src_in[idx];
        float ds = g_dinv1[s];
        float4 xs = X4[(size_t)s * 32 + lane];
        acc.x += ds * xs.x; acc.y += ds * xs.y;
        acc.z += ds * xs.z; acc.w += ds * xs.w;
    }
    float4 o = make_float4(di * acc.x, di * acc.y, di * acc.z, di * acc.w);
    ((float4*)g_aggX)[(size_t)i * 32 + lane] = o;
}

// ---------------- Wc = W1 @ fc1W  (128x256 @ 256x128) ----------------
__global__ __launch_bounds__(128) void k_wc(
    const float* __restrict__ W1, const float* __restrict__ fc1W)
{
    __shared__ float w1s[8][16];
    int f0 = blockIdx.x * 16;
    int tid = threadIdx.x; // d2 column
    float acc[16];
    #pragma unroll
    for (int f = 0; f < 16; f++) acc[f] = 0.f;
    for (int k0 = 0; k0 < D1; k0 += 8) {
        int kk = tid >> 4, ff = tid & 15;
        w1s[kk][ff] = W1[(size_t)(f0 + ff) * D1 + k0 + kk];
        __syncthreads();
        #pragma unroll
        for (int k = 0; k < 8; k++) {
            float b = fc1W[(size_t)(k0 + k) * D2 + tid];
            #pragma unroll
            for (int f = 0; f < 16; f++) acc[f] += w1s[k][f] * b;
        }
        __syncthreads();
    }
    #pragma unroll
    for (int f = 0; f < 16; f++) g_Wc[(size_t)(f0 + f) * D2 + tid] = acc[f];
}

// bc = b1 @ fc1W + fc1b
__global__ __launch_bounds__(128) void k_bc(
    const float* __restrict__ b1, const float* __restrict__ fc1W,
    const float* __restrict__ fc1b)
{
    int t = threadIdx.x;
    float acc = fc1b[t];
    for (int k = 0; k < D1; k++) acc += b1[k] * fc1W[(size_t)k * D2 + t];
    g_bc[t] = acc;
}

// ---------------- f32x2 GEMM: abs = tanh(aggX @ Wc + bc)  M=NN, N=128, K=128 ----------------
// 128x128 tile, BK=8, 256 threads, 8x8 microtile via packed fma.rn.f32x2.
// A tile stored DUPLICATED (each value twice, adjacent) so a 64-bit load yields (a,a).
__global__ __launch_bounds__(256) void k_gemm_abs() {
    const float* __restrict__ A = g_aggX;
    const float* __restrict__ B = g_Wc;
    __shared__ __align__(16) float As2[8][256]; // duplicated A: [k][2m],[2m+1]
    __shared__ __align__(16) float Bs[8][128];
    int tid = threadIdx.x;
    int m0 = blockIdx.x * 128;
    int tx = tid % 16, ty = tid / 16;

    int ar = tid >> 1, ak = (tid & 1) * 4;   // A fill: row, k-offset
    int bk = tid >> 5, bn = (tid & 31) * 4;  // B fill

    ull acc2[8][4];
    #pragma unroll
    for (int i = 0; i < 8; i++)
        #pragma unroll
        for (int j = 0; j < 4; j++) acc2[i][j] = 0ull;

    for (int k0 = 0; k0 < FIN; k0 += 8) {
        float4 av = make_float4(0.f, 0.f, 0.f, 0.f);
        if (m0 + ar < NN) av = *(const float4*)&A[(size_t)(m0 + ar) * FIN + k0 + ak];
        As2[ak + 0][2 * ar] = av.x; As2[ak + 0][2 * ar + 1] = av.x;
        As2[ak + 1][2 * ar] = av.y; As2[ak + 1][2 * ar + 1] = av.y;
        As2[ak + 2][2 * ar] = av.z; As2[ak + 2][2 * ar + 1] = av.z;
        As2[ak + 3][2 * ar] = av.w; As2[ak + 3][2 * ar + 1] = av.w;
        float4 bv = *(const float4*)&B[(size_t)(k0 + bk) * D2 + bn];
        *(float4*)&Bs[bk][bn] = bv;
        __syncthreads();
        #pragma unroll
        for (int k = 0; k < 8; k++) {
            ulonglong2 a01 = *(const ulonglong2*)&As2[k][ty * 16 + 0];
            ulonglong2 a23 = *(const ulonglong2*)&As2[k][ty * 16 + 4];
            ulonglong2 a45 = *(const ulonglong2*)&As2[k][ty * 16 + 8];
            ulonglong2 a67 = *(const ulonglong2*)&As2[k][ty * 16 + 12];
            ulonglong2 b01 = *(const ulonglong2*)&Bs[k][tx * 8 + 0];
            ulonglong2 b23 = *(const ulonglong2*)&Bs[k][tx * 8 + 4];
            ull aR[8] = {a01.x, a01.y, a23.x, a23.y, a45.x, a45.y, a67.x, a67.y};
            ull bR[4] = {b01.x, b01.y, b23.x, b23.y};
            #pragma unroll
            for (int i = 0; i < 8; i++)
                #pragma unroll
                for (int j = 0; j < 4; j++)
                    fma2(acc2[i][j], aR[i], bR[j]);
        }
        __syncthreads();
    }

    float bloc[8];
    #pragma unroll
    for (int j = 0; j < 8; j++) bloc[j] = g_bc[tx * 8 + j];
    #pragma unroll
    for (int i = 0; i < 8; i++) {
        int m = m0 + ty * 8 + i;
        if (m >= NN) continue;
        float v[8];
        #pragma unroll
        for (int j = 0; j < 4; j++) {
            v[2 * j + 0] = tanhf(ull_lo(acc2[i][j]) + bloc[2 * j + 0]);
            v[2 * j + 1] = tanhf(ull_hi(acc2[i][j]) + bloc[2 * j + 1]);
        }
        *(float4*)&g_abs[(size_t)m * D2 + tx * 8] = make_float4(v[0], v[1], v[2], v[3]);
        *(float4*)&g_abs[(size_t)m * D2 + tx * 8 + 4] = make_float4(v[4], v[5], v[6], v[7]);
    }
}

// ---------------- fused fc2 + softmax ----------------
__global__ __launch_bounds__(256) void k_fc2_softmax(
    const float* __restrict__ W, const float* __restrict__ b)
{
    __shared__ float Ws[D2 * KC];
    __shared__ float bs[KC];
    int tid = threadIdx.x;
    for (int j = tid; j < D2 * KC; j += blockDim.x) Ws[j] = W[j];
    if (tid < KC) bs[tid] = b[tid];
    __syncthreads();
    int lane = tid & 31, warp = tid >> 5;
    int nwarps = (blockDim.x >> 5) * gridDim.x;
    for (int i = blockIdx.x * (blockDim.x >> 5) + warp; i < NN; i += nwarps) {
        float areg[4];
        #pragma unroll
        for (int j = 0; j < 4; j++) areg[j] = g_abs[(size_t)i * D2 + j * 32 + lane];
        float acc = bs[lane];
        #pragma unroll
        for (int j = 0; j < 4; j++)
            #pragma unroll
            for (int d = 0; d < 32; d++) {
                float a = __shfl_sync(0xffffffffu, areg[j], d);
                acc += a * Ws[(j * 32 + d) * KC + lane];
            }
        float m = acc;
        #pragma unroll
        for (int o = 16; o > 0; o >>= 1) m = fmaxf(m, __shfl_xor_sync(0xffffffffu, m, o));
        float e = expf(acc - m);
        float s = e;
        #pragma unroll
        for (int o = 16; o > 0; o >>= 1) s += __shfl_xor_sync(0xffffffffu, s, o);
        g_S[(size_t)i * KC + lane] = e / s;
    }
}

// ---------------- fused Laplacian + adj: LS computed in regs, adj += S^T LS ----------------
__global__ __launch_bounds__(256) void k_lap_adj() {
    __shared__ float sh[8][KC * KC];
    int tid = threadIdx.x, lane = tid & 31, w = tid >> 5;
    float adjacc[32];
    #pragma unroll
    for (int a = 0; a < 32; a++) adjacc[a] = 0.f;
    int gw = blockIdx.x * 8 + w, tw = gridDim.x * 8;
    for (int i = gw; i < NN; i += tw) {
        float sv = g_S[(size_t)i * KC + lane];
        float di = g_dinv2[i];
        float ls = sv;
        int s0 = g_off_out[i], s1 = g_off_out[i + 1];
        for (int idx = s0; idx < s1; idx++) {
            int c = g_dst_out[idx];
            ls -= di * g_dinv2[c] * g_S[(size_t)c * KC + lane];
        }
        #pragma unroll
        for (int a = 0; a < 32; a++) {
            float sa = __shfl_sync(0xffffffffu, sv, a);
            adjacc[a] += sa * ls;
        }
    }
    #pragma unroll
    for (int a = 0; a < 32; a++) sh[w][a * 32 + lane] = adjacc[a];
    __syncthreads();
    for (int j = tid; j < KC * KC; j += blockDim.x) {
        float s = 0.f;
        #pragma unroll
        for (int w2 = 0; w2 < 8; w2++) s += sh[w2][j];
        atomicAdd(&g_adj[j], s);
    }
}

// ---------------- column sum of aggX ----------------
__global__ __launch_bounds__(128) void k_colsum() {
    int t = threadIdx.x; // 128 = FIN
    float acc = 0.f;
    for (int i = blockIdx.x; i < NN; i += gridDim.x)
        acc += g_aggX[(size_t)i * FIN + t];
    atomicAdd(&g_cs[t], acc);
}

// ---------------- finalize: emb = (cs@W1 + NN*b1)/32 ; pos_penalty ----------------
__global__ void k_final(const float* __restrict__ W1, const float* __restrict__ b1,
                        float* __restrict__ out, int out_size) {
    int t = threadIdx.x; // 256 = D1
    float acc = (float)NN * b1[t];
    for (int f = 0; f < FIN; f++) acc += g_cs[f] * W1[(size_t)f * D1 + t];
    if (t < out_size) out[t] = acc * (1.f / 32.f);
    if (t < 32) {
        float rs = 0.f;
        #pragma unroll
        for (int b = 0; b < 32; b++) rs += fabsf(g_adj[t * 32 + b]);
        float d = g_adj[t * 33] / fmaxf(rs, 1e-12f);
        float contrib = (d - 1.f) * (d - 1.f) + 31.f * d * d;
        #pragma unroll
        for (int o = 16; o > 0; o >>= 1) contrib += __shfl_xor_sync(0xffffffffu, contrib, o);
        if (t == 0 && out_size > D1) out[D1] = contrib * (1.f / 1024.f);
    }
}

// ---------------- launch ----------------
extern "C" void kernel_launch(void* const* d_in, const int* in_sizes, int n_in,
                              void* d_out, int out_size) {
    const float* feat  = (const float*)d_in[0];
    const int*   edges = (const int*)d_in[1];   // (2, E) int32
    const float* W1    = (const float*)d_in[2];
    const float* b1    = (const float*)d_in[3];
    const float* fc1W  = (const float*)d_in[4];
    const float* fc1b  = (const float*)d_in[5];
    const float* fc2W  = (const float*)d_in[6];
    const float* fc2b  = (const float*)d_in[7];
    float* out = (float*)d_out;

    k_zero<<<256, 256>>>();
    k_degree<<<1024, 256>>>(edges);
    k_scan2<<<2, 1024>>>();
    k_dinv<<<256, 256>>>();
    k_fill<<<1024, 256>>>(edges);
    k_agg<<<(NN + 7) / 8, 256>>>(feat);
    k_wc<<<8, 128>>>(W1, fc1W);
    k_bc<<<1, 128>>>(b1, fc1W, fc1b);
    k_gemm_abs<<<(NN + 127) / 128, 256>>>();
    k_fc2_softmax<<<296, 256>>>(fc2W, fc2b);
    k_lap_adj<<<74, 256>>>();
    k_colsum<<<512, 128>>>();
    k_final<<<1, 256>>>(W1, b1, out, out_size);
}

// round 8
// speedup vs baseline: 1.8234x; 1.8234x over previous
#include <cuda_runtime.h>
#include <math.h>
#include <stdint.h>

#define NN 50000
#define NE 800000
#define FIN 128
#define D1 256
#define D2 128
#define KC 32

// ---------------- scratch (device globals) ----------------
__device__ __align__(16) float g_aggX[(size_t)NN * FIN];  // normalized (A+I) agg of features
__device__ __align__(16) float g_abs[(size_t)NN * D2];    // tanh(aggX@Wc+bc)
__device__ __align__(16) float g_S[(size_t)NN * KC];      // softmax assign
__device__ __align__(16) float g_LS[(size_t)NN * KC];     // L @ S
__device__ __align__(16) float g_Wc[FIN * D2];            // W1 @ fc1W  (128x128) [k][n]
__device__ float g_bc[D2];                                 // b1 @ fc1W + fc1b
__device__ float g_cs[FIN];                                // colsum(aggX)
__device__ int   g_deg_in[NN], g_deg_out[NN];
__device__ int   g_off_in[NN + 1], g_off_out[NN + 1];
__device__ int   g_cur_in[NN], g_cur_out[NN];
__device__ int   g_src_in[NE];             // CSR by target: source ids
__device__ int   g_dst_out[NE];            // CSR by source: target ids
__device__ float g_dinv1[NN], g_dinv2[NN];
__device__ float g_adj[KC * KC];

// ---------------- init ----------------
__global__ void k_zero() {
    int i = blockIdx.x * blockDim.x + threadIdx.x;
    int stride = gridDim.x * blockDim.x;
    for (int j = i; j < NN; j += stride) {
        g_deg_in[j] = 0; g_deg_out[j] = 0;
        g_cur_in[j] = 0; g_cur_out[j] = 0;
    }
    if (i < KC * KC) g_adj[i] = 0.f;
    if (i < FIN) g_cs[i] = 0.f;
}

__global__ void k_degree(const int* __restrict__ e) {
    int i = blockIdx.x * blockDim.x + threadIdx.x;
    int stride = gridDim.x * blockDim.x;
    for (int j = i; j < NE; j += stride) {
        atomicAdd(&g_deg_out[e[j]], 1);
        atomicAdd(&g_deg_in[e[NE + j]], 1);
    }
}

// tiled block scan + dinv: block 0 scans deg_in (emits dinv1), block 1 deg_out (dinv2)
__global__ __launch_bounds__(1024) void k_scan2() {
    const int* cnt = blockIdx.x ? g_deg_out : g_deg_in;
    int* off = blockIdx.x ? g_off_out : g_off_in;
    __shared__ int wsum[32];
    __shared__ int carry;
    int t = threadIdx.x;
    int lane = t & 31, w = t >> 5;
    if (t == 0) carry = 0;
    __syncthreads();
    for (int base = 0; base < NN; base += 1024) {
        int idx = base + t;
        int v = (idx < NN) ? cnt[idx] : 0;
        if (idx < NN) {
            if (blockIdx.x == 0) g_dinv1[idx] = rsqrtf((float)(v + 1));
            else                 g_dinv2[idx] = (v > 0) ? rsqrtf((float)v) : 0.f;
        }
        int x = v;
        #pragma unroll
        for (int o = 1; o < 32; o <<= 1) {
            int y = __shfl_up_sync(0xffffffffu, x, o);
            if (lane >= o) x += y;
        }
        if (lane == 31) wsum[w] = x;
        __syncthreads();
        if (w == 0) {
            int s = wsum[lane];
            #pragma unroll
            for (int o = 1; o < 32; o <<= 1) {
                int y = __shfl_up_sync(0xffffffffu, s, o);
                if (lane >= o) s += y;
            }
            wsum[lane] = s;
        }
        __syncthreads();
        int incl = x + (w ? wsum[w - 1] : 0);
        if (idx < NN) off[idx] = carry + incl - v;
        int total = wsum[31];
        __syncthreads();
        if (t == 0) carry += total;
        __syncthreads();
    }
    if (t == 0) off[NN] = carry;
}

__global__ void k_fill(const int* __restrict__ e) {
    int i = blockIdx.x * blockDim.x + threadIdx.x;
    int stride = gridDim.x * blockDim.x;
    for (int j = i; j < NE; j += stride) {
        int r = e[j];
        int c = e[NE + j];
        int p = atomicAdd(&g_cur_in[c], 1);
        g_src_in[g_off_in[c] + p] = r;
        int q = atomicAdd(&g_cur_out[r], 1);
        g_dst_out[g_off_out[r] + q] = c;
    }
}

// ---------------- feature aggregation + fused column sum ----------------
// aggX[i] = di*(sum ds*X[s] + di*X[i]);  g_cs += colsum(aggX) (block-reduced)
__global__ __launch_bounds__(256) void k_agg(const float* __restrict__ X) {
    __shared__ float cs[8][FIN];
    int w = threadIdx.x >> 5;
    int lane = threadIdx.x & 31;
    int i = blockIdx.x * 8 + w;
    float4 o = make_float4(0.f, 0.f, 0.f, 0.f);
    if (i < NN) {
        float di = g_dinv1[i];
        const float4* X4 = (const float4*)X;
        float4 x = X4[(size_t)i * 32 + lane];
        float4 acc = make_float4(di * x.x, di * x.y, di * x.z, di * x.w);
        int s0 = g_off_in[i], s1 = g_off_in[i + 1];
        for (int idx = s0; idx < s1; idx++) {
            int s = g_src_in[idx];
            float ds = g_dinv1[s];
            float4 xs = X4[(size_t)s * 32 + lane];
            acc.x += ds * xs.x; acc.y += ds * xs.y;
            acc.z += ds * xs.z; acc.w += ds * xs.w;
        }
        o = make_float4(di * acc.x, di * acc.y, di * acc.z, di * acc.w);
        ((float4*)g_aggX)[(size_t)i * 32 + lane] = o;
    }
    *(float4*)&cs[w][lane * 4] = o;
    __syncthreads();
    if (threadIdx.x < FIN) {
        float s = 0.f;
        #pragma unroll
        for (int w2 = 0; w2 < 8; w2++) s += cs[w2][threadIdx.x];
        atomicAdd(&g_cs[threadIdx.x], s);
    }
}

// ---------------- Wc = W1 @ fc1W  (128x256 @ 256x128) ----------------
__global__ __launch_bounds__(128) void k_wc(
    const float* __restrict__ W1, const float* __restrict__ fc1W)
{
    __shared__ float w1s[8][16];
    int f0 = blockIdx.x * 16;
    int tid = threadIdx.x; // d2 column
    float acc[16];
    #pragma unroll
    for (int f = 0; f < 16; f++) acc[f] = 0.f;
    for (int k0 = 0; k0 < D1; k0 += 8) {
        int kk = tid >> 4, ff = tid & 15;
        w1s[kk][ff] = W1[(size_t)(f0 + ff) * D1 + k0 + kk];
        __syncthreads();
        #pragma unroll
        for (int k = 0; k < 8; k++) {
            float b = fc1W[(size_t)(k0 + k) * D2 + tid];
            #pragma unroll
            for (int f = 0; f < 16; f++) acc[f] += w1s[k][f] * b;
        }
        __syncthreads();
    }
    #pragma unroll
    for (int f = 0; f < 16; f++) g_Wc[(size_t)(f0 + f) * D2 + tid] = acc[f];
}

// bc = b1 @ fc1W + fc1b
__global__ __launch_bounds__(128) void k_bc(
    const float* __restrict__ b1, const float* __restrict__ fc1W,
    const float* __restrict__ fc1b)
{
    int t = threadIdx.x;
    float acc = fc1b[t];
    for (int k = 0; k < D1; k++) acc += b1[k] * fc1W[(size_t)k * D2 + t];
    g_bc[t] = acc;
}

// ---------------- SGEMM: abs = tanh(aggX @ Wc + bc), 64x128 tile, BK=8, 4x8 microtile ----------------
__global__ void __launch_bounds__(256, 4) k_gemm_abs() {
    const float* __restrict__ A = g_aggX;
    const float* __restrict__ B = g_Wc;
    __shared__ float As[8][64];
    __shared__ float Bs[8][128];
    int tid = threadIdx.x;
    int m0 = blockIdx.x * 64;
    int tx = tid % 16, ty = tid / 16;   // tx: 16 N-groups of 8; ty: 16 M-groups of 4

    int ar = tid >> 2, ak = (tid & 3) * 2;   // A fill: row 0..63, k pair
    int bk = tid >> 5, bn = (tid & 31) * 4;  // B fill

    float acc[4][8];
    #pragma unroll
    for (int i = 0; i < 4; i++)
        #pragma unroll
        for (int j = 0; j < 8; j++) acc[i][j] = 0.f;

    for (int k0 = 0; k0 < FIN; k0 += 8) {
        float2 av = make_float2(0.f, 0.f);
        if (m0 + ar < NN) av = *(const float2*)&A[(size_t)(m0 + ar) * FIN + k0 + ak];
        As[ak + 0][ar] = av.x;
        As[ak + 1][ar] = av.y;
        float4 bv = *(const float4*)&B[(size_t)(k0 + bk) * D2 + bn];
        *(float4*)&Bs[bk][bn] = bv;
        __syncthreads();
        #pragma unroll
        for (int k = 0; k < 8; k++) {
            float4 a0 = *(const float4*)&As[k][ty * 4];
            float4 b0 = *(const float4*)&Bs[k][tx * 8];
            float4 b1 = *(const float4*)&Bs[k][tx * 8 + 4];
            float aR[4] = {a0.x, a0.y, a0.z, a0.w};
            float bR[8] = {b0.x, b0.y, b0.z, b0.w, b1.x, b1.y, b1.z, b1.w};
            #pragma unroll
            for (int i = 0; i < 4; i++)
                #pragma unroll
                for (int j = 0; j < 8; j++)
                    acc[i][j] += aR[i] * bR[j];
        }
        __syncthreads();
    }

    float bloc[8];
    #pragma unroll
    for (int j = 0; j < 8; j++) bloc[j] = g_bc[tx * 8 + j];
    #pragma unroll
    for (int i = 0; i < 4; i++) {
        int m = m0 + ty * 4 + i;
        if (m >= NN) continue;
        float v[8];
        #pragma unroll
        for (int j = 0; j < 8; j++) v[j] = tanhf(acc[i][j] + bloc[j]);
        *(float4*)&g_abs[(size_t)m * D2 + tx * 8] = make_float4(v[0], v[1], v[2], v[3]);
        *(float4*)&g_abs[(size_t)m * D2 + tx * 8 + 4] = make_float4(v[4], v[5], v[6], v[7]);
    }
}

// ---------------- fused fc2 + softmax ----------------
__global__ __launch_bounds__(256) void k_fc2_softmax(
    const float* __restrict__ W, const float* __restrict__ b)
{
    __shared__ float Ws[D2 * KC];
    __shared__ float bs[KC];
    int tid = threadIdx.x;
    for (int j = tid; j < D2 * KC; j += blockDim.x) Ws[j] = W[j];
    if (tid < KC) bs[tid] = b[tid];
    __syncthreads();
    int lane = tid & 31, warp = tid >> 5;
    int nwarps = (blockDim.x >> 5) * gridDim.x;
    for (int i = blockIdx.x * (blockDim.x >> 5) + warp; i < NN; i += nwarps) {
        float areg[4];
        #pragma unroll
        for (int j = 0; j < 4; j++) areg[j] = g_abs[(size_t)i * D2 + j * 32 + lane];
        float acc = bs[lane];
        #pragma unroll
        for (int j = 0; j < 4; j++)
            #pragma unroll
            for (int d = 0; d < 32; d++) {
                float a = __shfl_sync(0xffffffffu, areg[j], d);
                acc += a * Ws[(j * 32 + d) * KC + lane];
            }
        float m = acc;
        #pragma unroll
        for (int o = 16; o > 0; o >>= 1) m = fmaxf(m, __shfl_xor_sync(0xffffffffu, m, o));
        float e = expf(acc - m);
        float s = e;
        #pragma unroll
        for (int o = 16; o > 0; o >>= 1) s += __shfl_xor_sync(0xffffffffu, s, o);
        g_S[(size_t)i * KC + lane] = e / s;
    }
}

// ---------------- Laplacian: LS[i] = S[i] - dinv2[i]*sum dinv2[c]*S[c] ----------------
__global__ __launch_bounds__(256) void k_lap() {
    int tid = blockIdx.x * blockDim.x + threadIdx.x;
    int lane = tid & 31;
    int i = tid >> 5;
    if (i >= NN) return;
    float acc = g_S[(size_t)i * KC + lane];
    float di = g_dinv2[i];
    int s0 = g_off_out[i], s1 = g_off_out[i + 1];
    for (int idx = s0; idx < s1; idx++) {
        int c = g_dst_out[idx];
        acc -= di * g_dinv2[c] * g_S[(size_t)c * KC + lane];
    }
    g_LS[(size_t)i * KC + lane] = acc;
}

// ---------------- new_adj = S^T @ LS ----------------
__global__ __launch_bounds__(256) void k_adj() {
    __shared__ float sh[8][KC * KC];
    int tid = threadIdx.x, lane = tid & 31, w = tid >> 5;
    float acc[32];
    #pragma unroll
    for (int a = 0; a < 32; a++) acc[a] = 0.f;
    int gw = blockIdx.x * 8 + w, tw = gridDim.x * 8;
    for (int i = gw; i < NN; i += tw) {
        float sv = g_S[(size_t)i * 32 + lane];
        float lv = g_LS[(size_t)i * 32 + lane];
        #pragma unroll
        for (int a = 0; a < 32; a++) {
            float sa = __shfl_sync(0xffffffffu, sv, a);
            acc[a] += sa * lv;
        }
    }
    #pragma unroll
    for (int a = 0; a < 32; a++) sh[w][a * 32 + lane] = acc[a];
    __syncthreads();
    for (int j = tid; j < KC * KC; j += blockDim.x) {
        float s = 0.f;
        #pragma unroll
        for (int w2 = 0; w2 < 8; w2++) s += sh[w2][j];
        atomicAdd(&g_adj[j], s);
    }
}

// ---------------- finalize: emb = (cs@W1 + NN*b1)/32 ; pos_penalty ----------------
__global__ void k_final(const float* __restrict__ W1, const float* __restrict__ b1,
                        float* __restrict__ out, int out_size) {
    int t = threadIdx.x; // 256 = D1
    float acc = (float)NN * b1[t];
    for (int f = 0; f < FIN; f++) acc += g_cs[f] * W1[(size_t)f * D1 + t];
    if (t < out_size) out[t] = acc * (1.f / 32.f);
    if (t < 32) {
        float rs = 0.f;
        #pragma unroll
        for (int b = 0; b < 32; b++) rs += fabsf(g_adj[t * 32 + b]);
        float d = g_adj[t * 33] / fmaxf(rs, 1e-12f);
        float contrib = (d - 1.f) * (d - 1.f) + 31.f * d * d;
        #pragma unroll
        for (int o = 16; o > 0; o >>= 1) contrib += __shfl_xor_sync(0xffffffffu, contrib, o);
        if (t == 0 && out_size > D1) out[D1] = contrib * (1.f / 1024.f);
    }
}

// ---------------- launch ----------------
extern "C" void kernel_launch(void* const* d_in, const int* in_sizes, int n_in,
                              void* d_out, int out_size) {
    const float* feat  = (const float*)d_in[0];
    const int*   edges = (const int*)d_in[1];   // (2, E) int32
    const float* W1    = (const float*)d_in[2];
    const float* b1    = (const float*)d_in[3];
    const float* fc1W  = (const float*)d_in[4];
    const float* fc1b  = (const float*)d_in[5];
    const float* fc2W  = (const float*)d_in[6];
    const float* fc2b  = (const float*)d_in[7];
    float* out = (float*)d_out;

    k_zero<<<256, 256>>>();
    k_degree<<<1024, 256>>>(edges);
    k_scan2<<<2, 1024>>>();
    k_fill<<<1024, 256>>>(edges);
    k_wc<<<8, 128>>>(W1, fc1W);
    k_bc<<<1, 128>>>(b1, fc1W, fc1b);
    k_agg<<<(NN + 7) / 8, 256>>>(feat);
    k_gemm_abs<<<(NN + 63) / 64, 256>>>();
    k_fc2_softmax<<<296, 256>>>(fc2W, fc2b);
    k_lap<<<(NN * 32 + 255) / 256, 256>>>();
    k_adj<<<148, 256>>>();
    k_final<<<1, 256>>>(W1, b1, out, out_size);
}